// round 1
// baseline (speedup 1.0000x reference)
#include <cuda_runtime.h>
#include <cstdint>

// ---------------------------------------------------------------------------
// ConstrainedEnhancementModel: 6-layer MLP + knot/linear-interp mixing.
// B=512, L=256, F=32, H=4096, HID=512, UP=16.
//   x  = low.reshape(512, 8192)
//   h1 = relu(x @ w1 + b1)        (512,1024)   K=8192
//   h2 = relu(h1 @ w2 + b2)       (512, 512)   K=1024
//   fe =      h2 @ w3 + b3        (512, 256)   K=512
//   d1 = relu(fe @ w4 + b4)       (512, 512)   K=256
//   d2 = relu(d1 @ w5 + b5)       (512,1024)   K=512
//   dec=      d2 @ w6 + b6        (512,131072) K=1024   <-- dominant GEMM
//   out mixing fused into GEMM6 epilogue.
// Round 1: pure fp32 SIMT tiled SGEMM baseline (exact precision).
// ---------------------------------------------------------------------------

#define NB   512
#define NL   256
#define NF   32
#define NH   4096
#define NOUTCOL (NH * NF)          // 131072
#define LAST_KNOT ((NL - 1) * 16)  // 4080

// Scratch (device globals; allocation-free rule)
__device__ float g_h1[512 * 1024];
__device__ float g_h2[512 * 512];
__device__ float g_fe[512 * 256];
__device__ float g_d1[512 * 512];
__device__ float g_d2[512 * 1024];

// ---------------------------------------------------------------------------
// Generic tiled SGEMM:  C = [relu](A(MxK,row) @ B(KxN,row) + bias)
// Requires: M % BM == 0, N % BN == 0, K % BK == 0, BK % 4 == 0, BN % 4 == 0.
// ---------------------------------------------------------------------------
template <int BM, int BN, int BK, int TM, int TN, bool RELU>
__global__ __launch_bounds__((BM / TM) * (BN / TN))
void sgemm_bias(const float* __restrict__ A, const float* __restrict__ Bm,
                const float* __restrict__ bias, float* __restrict__ C,
                int M, int N, int K)
{
    constexpr int THREADS = (BM / TM) * (BN / TN);
    __shared__ float As[BK][BM + 4];   // +4 pad kills STS bank conflicts
    __shared__ float Bs[BK][BN];

    const int tid = threadIdx.x;
    const int bn  = blockIdx.x * BN;
    const int bm  = blockIdx.y * BM;
    const int tx  = tid % (BN / TN);
    const int ty  = tid / (BN / TN);

    float acc[TM][TN];
#pragma unroll
    for (int i = 0; i < TM; i++)
#pragma unroll
        for (int j = 0; j < TN; j++) acc[i][j] = 0.0f;

    constexpr int AV = BK / 4;        // float4 per A tile row
    constexpr int AT = BM * AV;       // total A float4 loads
    constexpr int BV = BN / 4;
    constexpr int BT = BK * BV;

    for (int k0 = 0; k0 < K; k0 += BK) {
        for (int i = tid; i < AT; i += THREADS) {
            int r  = i / AV;
            int c4 = (i % AV) * 4;
            float4 v = *reinterpret_cast<const float4*>(
                A + (size_t)(bm + r) * K + k0 + c4);
            As[c4 + 0][r] = v.x;
            As[c4 + 1][r] = v.y;
            As[c4 + 2][r] = v.z;
            As[c4 + 3][r] = v.w;
        }
        for (int i = tid; i < BT; i += THREADS) {
            int r  = i / BV;
            int c4 = (i % BV) * 4;
            *reinterpret_cast<float4*>(&Bs[r][c4]) =
                *reinterpret_cast<const float4*>(
                    Bm + (size_t)(k0 + r) * N + bn + c4);
        }
        __syncthreads();

#pragma unroll
        for (int kk = 0; kk < BK; kk++) {
            float ra[TM], rb[TN];
#pragma unroll
            for (int i = 0; i < TM; i += 4)
                *reinterpret_cast<float4*>(&ra[i]) =
                    *reinterpret_cast<const float4*>(&As[kk][ty * TM + i]);
#pragma unroll
            for (int j = 0; j < TN; j += 4)
                *reinterpret_cast<float4*>(&rb[j]) =
                    *reinterpret_cast<const float4*>(&Bs[kk][tx * TN + j]);
#pragma unroll
            for (int i = 0; i < TM; i++)
#pragma unroll
                for (int j = 0; j < TN; j++)
                    acc[i][j] = fmaf(ra[i], rb[j], acc[i][j]);
        }
        __syncthreads();
    }

#pragma unroll
    for (int i = 0; i < TM; i++) {
        int row = bm + ty * TM + i;
#pragma unroll
        for (int j = 0; j < TN; j += 4) {
            int col = bn + tx * TN + j;
            float4 v;
            v.x = acc[i][j + 0] + bias[col + 0];
            v.y = acc[i][j + 1] + bias[col + 1];
            v.z = acc[i][j + 2] + bias[col + 2];
            v.w = acc[i][j + 3] + bias[col + 3];
            if (RELU) {
                v.x = fmaxf(v.x, 0.0f);
                v.y = fmaxf(v.y, 0.0f);
                v.z = fmaxf(v.z, 0.0f);
                v.w = fmaxf(v.w, 0.0f);
            }
            *reinterpret_cast<float4*>(C + (size_t)row * N + col) = v;
        }
    }
}

// ---------------------------------------------------------------------------
// GEMM6 with fused knot/interp epilogue.
//   dec[b, c] = (d2 @ w6 + b6)[b, c],  c = t*32 + f
//   t knot (t%16==0)        -> out = low[b, t/16, f]
//   t < 4080, not knot      -> out = 0.8*((1-a)*low[b,seg,f] + a*low[b,seg+1,f]) + 0.2*dec
//   else                    -> out = dec
// Tile: 128x128x8, 256 threads, 8x8 per thread. Each thread's 8 output
// columns are contiguous and never cross a t boundary (8 | 32).
// ---------------------------------------------------------------------------
__global__ __launch_bounds__(256)
void gemm6_fused(const float* __restrict__ A,    // d2: 512 x 1024
                 const float* __restrict__ Bm,   // w6: 1024 x 131072
                 const float* __restrict__ bias, // b6: 131072
                 const float* __restrict__ low,  // 512 x 256 x 32
                 float* __restrict__ out)        // 512 x 4096 x 32
{
    constexpr int BM = 128, BN = 128, BK = 8, TM = 8, TN = 8;
    constexpr int THREADS = 256;
    const int K = 1024;
    const int N = NOUTCOL;

    __shared__ float As[BK][BM + 4];
    __shared__ float Bs[BK][BN];

    const int tid = threadIdx.x;
    const int bn  = blockIdx.x * BN;
    const int bm  = blockIdx.y * BM;
    const int tx  = tid % (BN / TN);  // 0..15
    const int ty  = tid / (BN / TN);  // 0..15

    float acc[TM][TN];
#pragma unroll
    for (int i = 0; i < TM; i++)
#pragma unroll
        for (int j = 0; j < TN; j++) acc[i][j] = 0.0f;

    constexpr int AV = BK / 4;   // 2
    constexpr int AT = BM * AV;  // 256
    constexpr int BV = BN / 4;   // 32
    constexpr int BT = BK * BV;  // 256

    for (int k0 = 0; k0 < K; k0 += BK) {
        {
            int i  = tid;               // AT == THREADS
            int r  = i / AV;
            int c4 = (i % AV) * 4;
            float4 v = *reinterpret_cast<const float4*>(
                A + (size_t)(bm + r) * K + k0 + c4);
            As[c4 + 0][r] = v.x;
            As[c4 + 1][r] = v.y;
            As[c4 + 2][r] = v.z;
            As[c4 + 3][r] = v.w;
        }
        {
            int i  = tid;               // BT == THREADS
            int r  = i / BV;
            int c4 = (i % BV) * 4;
            *reinterpret_cast<float4*>(&Bs[r][c4]) =
                *reinterpret_cast<const float4*>(
                    Bm + (size_t)(k0 + r) * N + bn + c4);
        }
        __syncthreads();

#pragma unroll
        for (int kk = 0; kk < BK; kk++) {
            float ra[TM], rb[TN];
#pragma unroll
            for (int i = 0; i < TM; i += 4)
                *reinterpret_cast<float4*>(&ra[i]) =
                    *reinterpret_cast<const float4*>(&As[kk][ty * TM + i]);
#pragma unroll
            for (int j = 0; j < TN; j += 4)
                *reinterpret_cast<float4*>(&rb[j]) =
                    *reinterpret_cast<const float4*>(&Bs[kk][tx * TN + j]);
#pragma unroll
            for (int i = 0; i < TM; i++)
#pragma unroll
                for (int j = 0; j < TN; j++)
                    acc[i][j] = fmaf(ra[i], rb[j], acc[i][j]);
        }
        __syncthreads();
    }

    // ---- fused epilogue ----
    const int colBase = bn + tx * TN;       // multiple of 8; one t per thread
    const int t   = colBase >> 5;           // 0..4095
    const int rem = t & 15;
    const int seg = t >> 4;                 // 0..255
    const int f0  = colBase & 31;           // 0,8,16,24
    const bool knot  = (rem == 0);
    const bool inseg = (!knot) && (t < LAST_KNOT);
    const float alpha = (float)rem * 0.0625f;
    const int segB = (seg + 1 < NL) ? (seg + 1) : (NL - 1);  // clamp for safe load

    float bsv[TN];
#pragma unroll
    for (int q = 0; q < TN; q++) bsv[q] = bias[colBase + q];

#pragma unroll
    for (int i = 0; i < TM; i++) {
        const int b = bm + ty * TM + i;
        const float* lpA = low + (size_t)b * (NL * NF) + seg  * NF + f0;
        const float* lpB = low + (size_t)b * (NL * NF) + segB * NF + f0;
        float la[8], lb[8];
        *reinterpret_cast<float4*>(&la[0]) = *reinterpret_cast<const float4*>(lpA);
        *reinterpret_cast<float4*>(&la[4]) = *reinterpret_cast<const float4*>(lpA + 4);
        *reinterpret_cast<float4*>(&lb[0]) = *reinterpret_cast<const float4*>(lpB);
        *reinterpret_cast<float4*>(&lb[4]) = *reinterpret_cast<const float4*>(lpB + 4);

        float res[8];
#pragma unroll
        for (int q = 0; q < TN; q++) {
            float dec = acc[i][q] + bsv[q];
            float lin = (1.0f - alpha) * la[q] + alpha * lb[q];
            float sm  = 0.8f * lin + 0.2f * dec;
            res[q] = knot ? la[q] : (inseg ? sm : dec);
        }
        float* op = out + (size_t)b * NOUTCOL + colBase;
        *reinterpret_cast<float4*>(op)     = *reinterpret_cast<float4*>(&res[0]);
        *reinterpret_cast<float4*>(op + 4) = *reinterpret_cast<float4*>(&res[4]);
    }
}

// ---------------------------------------------------------------------------
extern "C" void kernel_launch(void* const* d_in, const int* in_sizes, int n_in,
                              void* d_out, int out_size)
{
    const float* low = (const float*)d_in[0];
    const float* w1  = (const float*)d_in[1];
    const float* b1  = (const float*)d_in[2];
    const float* w2  = (const float*)d_in[3];
    const float* b2  = (const float*)d_in[4];
    const float* w3  = (const float*)d_in[5];
    const float* b3  = (const float*)d_in[6];
    const float* w4  = (const float*)d_in[7];
    const float* b4  = (const float*)d_in[8];
    const float* w5  = (const float*)d_in[9];
    const float* b5  = (const float*)d_in[10];
    const float* w6  = (const float*)d_in[11];
    const float* b6  = (const float*)d_in[12];
    float* out = (float*)d_out;

    float *h1, *h2, *fe, *d1, *d2;
    cudaGetSymbolAddress((void**)&h1, g_h1);
    cudaGetSymbolAddress((void**)&h2, g_h2);
    cudaGetSymbolAddress((void**)&fe, g_fe);
    cudaGetSymbolAddress((void**)&d1, g_d1);
    cudaGetSymbolAddress((void**)&d2, g_d2);

    // L1: (512x8192)@(8192x1024) + relu
    sgemm_bias<64, 64, 16, 4, 4, true>
        <<<dim3(1024 / 64, 512 / 64), 256>>>(low, w1, b1, h1, 512, 1024, 8192);
    // L2: (512x1024)@(1024x512) + relu
    sgemm_bias<64, 64, 16, 4, 4, true>
        <<<dim3(512 / 64, 512 / 64), 256>>>(h1, w2, b2, h2, 512, 512, 1024);
    // L3: (512x512)@(512x256)   (no relu)
    sgemm_bias<64, 64, 16, 4, 4, false>
        <<<dim3(256 / 64, 512 / 64), 256>>>(h2, w3, b3, fe, 512, 256, 512);
    // L4: (512x256)@(256x512) + relu
    sgemm_bias<64, 64, 16, 4, 4, true>
        <<<dim3(512 / 64, 512 / 64), 256>>>(fe, w4, b4, d1, 512, 512, 256);
    // L5: (512x512)@(512x1024) + relu
    sgemm_bias<64, 64, 16, 4, 4, true>
        <<<dim3(1024 / 64, 512 / 64), 256>>>(d1, w5, b5, d2, 512, 1024, 512);
    // L6: (512x1024)@(1024x131072) + fused interp/knot epilogue
    gemm6_fused<<<dim3(NOUTCOL / 128, 512 / 128), 256>>>(d2, w6, b6, low, out);
}

// round 3
// speedup vs baseline: 3.1965x; 3.1965x over previous
#include <cuda_runtime.h>
#include <cstdint>

// ---------------------------------------------------------------------------
// ConstrainedEnhancementModel on GB300 (sm_103a host, but ptxas target is
// plain sm_103 -> no tcgen05/'a' features). R3: GEMM6 uses mma.sync tf32
// (sm_80+ baseline feature) with cp.async 4-stage pipeline and fused
// knot/interp epilogue. Small layers stay on R1 SIMT SGEMM.
// ---------------------------------------------------------------------------

#define NB   512
#define NL   256
#define NF   32
#define NH   4096
#define NOUTCOL (NH * NF)          // 131072
#define LAST_KNOT ((NL - 1) * 16)  // 4080

// Scratch (device globals; allocation-free rule)
__device__ float g_h1[512 * 1024];
__device__ float g_h2[512 * 512];
__device__ float g_fe[512 * 256];
__device__ float g_d1[512 * 512];
__device__ float g_d2[512 * 1024];

// ===========================================================================
// helpers
// ===========================================================================
__device__ __forceinline__ uint32_t smem_u32(const void* p) {
    uint32_t a;
    asm("{ .reg .u64 t; cvta.to.shared.u64 t, %1; cvt.u32.u64 %0, t; }"
        : "=r"(a) : "l"(p));
    return a;
}
__device__ __forceinline__ uint32_t to_tf32(float x) {
    uint32_t u;
    asm("cvt.rna.tf32.f32 %0, %1;" : "=r"(u) : "f"(x));
    return u;
}
__device__ __forceinline__ void cp16_ca(uint32_t dst, const void* src) {
    asm volatile("cp.async.ca.shared.global [%0], [%1], 16;"
                 :: "r"(dst), "l"(src) : "memory");
}
__device__ __forceinline__ void cp16_cg(uint32_t dst, const void* src) {
    asm volatile("cp.async.cg.shared.global [%0], [%1], 16;"
                 :: "r"(dst), "l"(src) : "memory");
}
#define CP_COMMIT() asm volatile("cp.async.commit_group;" ::: "memory")
#define CP_WAIT2()  asm volatile("cp.async.wait_group 2;" ::: "memory")

__device__ __forceinline__ void mma_tf32(float& c0, float& c1, float& c2, float& c3,
                                         uint32_t a0, uint32_t a1, uint32_t a2, uint32_t a3,
                                         uint32_t b0, uint32_t b1) {
    asm volatile(
        "mma.sync.aligned.m16n8k8.row.col.f32.tf32.tf32.f32 "
        "{%0,%1,%2,%3}, {%4,%5,%6,%7}, {%8,%9}, {%0,%1,%2,%3};"
        : "+f"(c0), "+f"(c1), "+f"(c2), "+f"(c3)
        : "r"(a0), "r"(a1), "r"(a2), "r"(a3), "r"(b0), "r"(b1));
}

// ===========================================================================
// GEMM6: out = epilogue( d2(512x1024) @ w6(1024x131072) + b6 )
// CTA tile 128(M) x 128(N), K-step 8, 4-stage cp.async pipeline.
// 8 warps: warp grid 2(M) x 4(N), warp tile 64x32  ->  each warp spans
// exactly one t (=col/32), so knot/interp parameters are warp-uniform.
// smem pitches: A 12 floats/row (banks 12g+c distinct),
//               B 136 floats/row (banks 8q+g = 0..31 perfect).
// ===========================================================================
#define G6_STAGES 4
#define G6_APITCH 12              // floats per A row (8 data + 4 pad)
#define G6_BPITCH 136             // floats per B row (128 data + 8 pad)
#define G6_ASTG   (128 * G6_APITCH)   // 1536 floats
#define G6_BSTG   (8 * G6_BPITCH)     // 1088 floats
#define G6_NKT    128             // 1024 / 8

__global__ void __launch_bounds__(256, 2)
gemm6_mma(const float* __restrict__ A,    // d2: 512 x 1024
          const float* __restrict__ Bm,   // w6: 1024 x 131072
          const float* __restrict__ bias, // b6: 131072
          const float* __restrict__ low,  // 512 x 256 x 32
          float* __restrict__ out)        // 512 x 4096 x 32
{
    __shared__ float As[G6_STAGES][G6_ASTG];
    __shared__ float Bs[G6_STAGES][G6_BSTG];
    __shared__ float sbias[128];

    const int tid  = threadIdx.x;
    const int wid  = tid >> 5;
    const int lane = tid & 31;
    const int g    = lane >> 2;    // group id 0..7
    const int q    = lane & 3;     // tid in group 0..3

    const int bm = blockIdx.x * 128;   // M block (4 total, fastest -> share w6)
    const int bn = blockIdx.y * 128;   // N block (1024 total)

    const int wm = (wid >> 2) * 64;    // warp M offset (0/64)
    const int wn = (wid & 3) * 32;     // warp N offset (0..96)

    const uint32_t AsA = smem_u32(&As[0][0]);
    const uint32_t BsA = smem_u32(&Bs[0][0]);

    // bias preload
    if (tid < 128) sbias[tid] = bias[bn + tid];

    // per-thread cp.async coordinates
    const int arow = tid >> 1, ach = tid & 1;          // A: 128 rows x 2 chunks
    const int brow = tid >> 5, bch = tid & 31;         // B: 8 rows x 32 chunks
    const float* aSrcBase = A + (size_t)(bm + arow) * 1024 + ach * 4;
    const float* bSrcBase = Bm + (size_t)brow * NOUTCOL + bn + bch * 4;
    const uint32_t aDst0 = AsA + (uint32_t)(arow * G6_APITCH + ach * 4) * 4;
    const uint32_t bDst0 = BsA + (uint32_t)(brow * G6_BPITCH + bch * 4) * 4;

#define G6_LOAD(s, kt)                                                        \
    do {                                                                      \
        cp16_ca(aDst0 + (s) * G6_ASTG * 4, aSrcBase + (kt) * 8);              \
        cp16_cg(bDst0 + (s) * G6_BSTG * 4,                                    \
                bSrcBase + (size_t)(kt) * 8 * NOUTCOL);                       \
    } while (0)

    // prologue: stages 0,1,2
    G6_LOAD(0, 0); CP_COMMIT();
    G6_LOAD(1, 1); CP_COMMIT();
    G6_LOAD(2, 2); CP_COMMIT();

    float acc[4][4][4];
#pragma unroll
    for (int i = 0; i < 4; i++)
#pragma unroll
        for (int j = 0; j < 4; j++)
#pragma unroll
            for (int k = 0; k < 4; k++) acc[i][j][k] = 0.0f;

    for (int kt = 0; kt < G6_NKT; kt++) {
        const int s = kt & (G6_STAGES - 1);
        CP_WAIT2();
        __syncthreads();
        if (kt + 3 < G6_NKT) {
            G6_LOAD((kt + 3) & (G6_STAGES - 1), kt + 3);
        }
        CP_COMMIT();

        const float* as = &As[s][0];
        const float* bs = &Bs[s][0];

        // B fragments: 4 n-tiles
        uint32_t bf[4][2];
#pragma unroll
        for (int nt = 0; nt < 4; nt++) {
            const int col = wn + nt * 8 + g;
            bf[nt][0] = to_tf32(bs[q * G6_BPITCH + col]);
            bf[nt][1] = to_tf32(bs[(q + 4) * G6_BPITCH + col]);
        }
        // A fragments + MMAs: 4 m-tiles
#pragma unroll
        for (int mt = 0; mt < 4; mt++) {
            const int r0 = wm + mt * 16 + g;
            uint32_t a0 = to_tf32(as[r0 * G6_APITCH + q]);
            uint32_t a1 = to_tf32(as[(r0 + 8) * G6_APITCH + q]);
            uint32_t a2 = to_tf32(as[r0 * G6_APITCH + q + 4]);
            uint32_t a3 = to_tf32(as[(r0 + 8) * G6_APITCH + q + 4]);
#pragma unroll
            for (int nt = 0; nt < 4; nt++)
                mma_tf32(acc[mt][nt][0], acc[mt][nt][1],
                         acc[mt][nt][2], acc[mt][nt][3],
                         a0, a1, a2, a3, bf[nt][0], bf[nt][1]);
        }
    }

    // ---- fused epilogue (warp-uniform t) ----
    const int t   = (bn + wn) >> 5;
    const int rem = t & 15;
    const int seg = t >> 4;
    const bool knot  = (rem == 0);
    const bool inseg = (!knot) && (t < LAST_KNOT);
    const float alpha = (float)rem * 0.0625f;
    const int segB = (seg < NL - 1) ? seg + 1 : NL - 1;

#pragma unroll
    for (int mt = 0; mt < 4; mt++) {
#pragma unroll
        for (int h = 0; h < 2; h++) {
            const int r = bm + wm + mt * 16 + g + h * 8;
            const float* lowr = low + (size_t)r * (NL * NF);
            float* outr = out + (size_t)r * NOUTCOL + bn + wn;
#pragma unroll
            for (int nt = 0; nt < 4; nt++) {
                const int f = nt * 8 + 2 * q;
                float dec0 = acc[mt][nt][2 * h]     + sbias[wn + f];
                float dec1 = acc[mt][nt][2 * h + 1] + sbias[wn + f + 1];
                float2 la = *reinterpret_cast<const float2*>(lowr + seg  * NF + f);
                float2 lb = *reinterpret_cast<const float2*>(lowr + segB * NF + f);
                float lin0 = (1.0f - alpha) * la.x + alpha * lb.x;
                float lin1 = (1.0f - alpha) * la.y + alpha * lb.y;
                float r0 = knot ? la.x : (inseg ? 0.8f * lin0 + 0.2f * dec0 : dec0);
                float r1 = knot ? la.y : (inseg ? 0.8f * lin1 + 0.2f * dec1 : dec1);
                float2 v = make_float2(r0, r1);
                *reinterpret_cast<float2*>(outr + f) = v;
            }
        }
    }
#undef G6_LOAD
}

// ===========================================================================
// Small-layer SIMT SGEMM (unchanged from R1)
// ===========================================================================
template <int BM, int BN, int BK, int TM, int TN, bool RELU>
__global__ __launch_bounds__((BM / TM) * (BN / TN))
void sgemm_bias(const float* __restrict__ A, const float* __restrict__ Bm,
                const float* __restrict__ bias, float* __restrict__ C,
                int M, int N, int K)
{
    constexpr int THREADS = (BM / TM) * (BN / TN);
    __shared__ float As[BK][BM + 4];
    __shared__ float Bs[BK][BN];

    const int tid = threadIdx.x;
    const int bn  = blockIdx.x * BN;
    const int bm  = blockIdx.y * BM;
    const int tx  = tid % (BN / TN);
    const int ty  = tid / (BN / TN);

    float acc[TM][TN];
#pragma unroll
    for (int i = 0; i < TM; i++)
#pragma unroll
        for (int j = 0; j < TN; j++) acc[i][j] = 0.0f;

    constexpr int AV = BK / 4;
    constexpr int AT = BM * AV;
    constexpr int BV = BN / 4;
    constexpr int BT = BK * BV;

    for (int k0 = 0; k0 < K; k0 += BK) {
        for (int i = tid; i < AT; i += THREADS) {
            int r  = i / AV;
            int c4 = (i % AV) * 4;
            float4 v = *reinterpret_cast<const float4*>(
                A + (size_t)(bm + r) * K + k0 + c4);
            As[c4 + 0][r] = v.x;
            As[c4 + 1][r] = v.y;
            As[c4 + 2][r] = v.z;
            As[c4 + 3][r] = v.w;
        }
        for (int i = tid; i < BT; i += THREADS) {
            int r  = i / BV;
            int c4 = (i % BV) * 4;
            *reinterpret_cast<float4*>(&Bs[r][c4]) =
                *reinterpret_cast<const float4*>(
                    Bm + (size_t)(k0 + r) * N + bn + c4);
        }
        __syncthreads();

#pragma unroll
        for (int kk = 0; kk < BK; kk++) {
            float ra[TM], rb[TN];
#pragma unroll
            for (int i = 0; i < TM; i += 4)
                *reinterpret_cast<float4*>(&ra[i]) =
                    *reinterpret_cast<const float4*>(&As[kk][ty * TM + i]);
#pragma unroll
            for (int j = 0; j < TN; j += 4)
                *reinterpret_cast<float4*>(&rb[j]) =
                    *reinterpret_cast<const float4*>(&Bs[kk][tx * TN + j]);
#pragma unroll
            for (int i = 0; i < TM; i++)
#pragma unroll
                for (int j = 0; j < TN; j++)
                    acc[i][j] = fmaf(ra[i], rb[j], acc[i][j]);
        }
        __syncthreads();
    }

#pragma unroll
    for (int i = 0; i < TM; i++) {
        int row = bm + ty * TM + i;
#pragma unroll
        for (int j = 0; j < TN; j += 4) {
            int col = bn + tx * TN + j;
            float4 v;
            v.x = acc[i][j + 0] + bias[col + 0];
            v.y = acc[i][j + 1] + bias[col + 1];
            v.z = acc[i][j + 2] + bias[col + 2];
            v.w = acc[i][j + 3] + bias[col + 3];
            if (RELU) {
                v.x = fmaxf(v.x, 0.0f);
                v.y = fmaxf(v.y, 0.0f);
                v.z = fmaxf(v.z, 0.0f);
                v.w = fmaxf(v.w, 0.0f);
            }
            *reinterpret_cast<float4*>(C + (size_t)row * N + col) = v;
        }
    }
}

// ---------------------------------------------------------------------------
extern "C" void kernel_launch(void* const* d_in, const int* in_sizes, int n_in,
                              void* d_out, int out_size)
{
    const float* low = (const float*)d_in[0];
    const float* w1  = (const float*)d_in[1];
    const float* b1  = (const float*)d_in[2];
    const float* w2  = (const float*)d_in[3];
    const float* b2  = (const float*)d_in[4];
    const float* w3  = (const float*)d_in[5];
    const float* b3  = (const float*)d_in[6];
    const float* w4  = (const float*)d_in[7];
    const float* b4  = (const float*)d_in[8];
    const float* w5  = (const float*)d_in[9];
    const float* b5  = (const float*)d_in[10];
    const float* w6  = (const float*)d_in[11];
    const float* b6  = (const float*)d_in[12];
    float* out = (float*)d_out;

    float *h1, *h2, *fe, *d1, *d2;
    cudaGetSymbolAddress((void**)&h1, g_h1);
    cudaGetSymbolAddress((void**)&h2, g_h2);
    cudaGetSymbolAddress((void**)&fe, g_fe);
    cudaGetSymbolAddress((void**)&d1, g_d1);
    cudaGetSymbolAddress((void**)&d2, g_d2);

    // L1: (512x8192)@(8192x1024) + relu
    sgemm_bias<64, 64, 16, 4, 4, true>
        <<<dim3(1024 / 64, 512 / 64), 256>>>(low, w1, b1, h1, 512, 1024, 8192);
    // L2: (512x1024)@(1024x512) + relu
    sgemm_bias<64, 64, 16, 4, 4, true>
        <<<dim3(512 / 64, 512 / 64), 256>>>(h1, w2, b2, h2, 512, 512, 1024);
    // L3: (512x512)@(512x256)
    sgemm_bias<64, 64, 16, 4, 4, false>
        <<<dim3(256 / 64, 512 / 64), 256>>>(h2, w3, b3, fe, 512, 256, 512);
    // L4: (512x256)@(256x512) + relu
    sgemm_bias<64, 64, 16, 4, 4, true>
        <<<dim3(512 / 64, 512 / 64), 256>>>(fe, w4, b4, d1, 512, 512, 256);
    // L5: (512x512)@(512x1024) + relu
    sgemm_bias<64, 64, 16, 4, 4, true>
        <<<dim3(1024 / 64, 512 / 64), 256>>>(d1, w5, b5, d2, 512, 1024, 512);
    // L6: mma.sync tf32 + fused epilogue. grid.x = M blocks (fastest) so the
    // 4 CTAs sharing each w6 column strip are co-resident (L2 dedup).
    gemm6_mma<<<dim3(4, NOUTCOL / 128), 256>>>(d2, w6, b6, low, out);
}

// round 4
// speedup vs baseline: 3.8166x; 1.1940x over previous
#include <cuda_runtime.h>
#include <cuda_fp16.h>
#include <cstdint>

// ---------------------------------------------------------------------------
// ConstrainedEnhancementModel on GB300 (ptxas target sm_103: no 'a' features).
// R4: GEMM6 in fp16 mma.sync m16n8k16. w6 is transpose-converted to fp16
// [n][k] once per call; d2 produced in fp16 by L5. Fused knot/interp epilogue.
// ---------------------------------------------------------------------------

#define NB   512
#define NL   256
#define NF   32
#define NH   4096
#define NOUTCOL (NH * NF)          // 131072
#define LAST_KNOT ((NL - 1) * 16)  // 4080

// Scratch (device globals; allocation-free rule)
__device__ float  g_h1[512 * 1024];
__device__ float  g_h2[512 * 512];
__device__ float  g_fe[512 * 256];
__device__ float  g_d1[512 * 512];
__device__ __half g_d2h[512 * 1024];
__device__ __half g_w6t[(size_t)NOUTCOL * 1024];   // 256 MB, [n][k] fp16

// ===========================================================================
// helpers
// ===========================================================================
__device__ __forceinline__ uint32_t smem_u32(const void* p) {
    uint32_t a;
    asm("{ .reg .u64 t; cvta.to.shared.u64 t, %1; cvt.u32.u64 %0, t; }"
        : "=r"(a) : "l"(p));
    return a;
}
__device__ __forceinline__ void cp16_ca(uint32_t dst, const void* src) {
    asm volatile("cp.async.ca.shared.global [%0], [%1], 16;"
                 :: "r"(dst), "l"(src) : "memory");
}
__device__ __forceinline__ void cp16_cg(uint32_t dst, const void* src) {
    asm volatile("cp.async.cg.shared.global [%0], [%1], 16;"
                 :: "r"(dst), "l"(src) : "memory");
}
#define CP_COMMIT() asm volatile("cp.async.commit_group;" ::: "memory")
#define CP_WAIT2()  asm volatile("cp.async.wait_group 2;" ::: "memory")

__device__ __forceinline__ void mma_fp16(float& c0, float& c1, float& c2, float& c3,
                                         uint32_t a0, uint32_t a1, uint32_t a2, uint32_t a3,
                                         uint32_t b0, uint32_t b1) {
    asm volatile(
        "mma.sync.aligned.m16n8k16.row.col.f32.f16.f16.f32 "
        "{%0,%1,%2,%3}, {%4,%5,%6,%7}, {%8,%9}, {%0,%1,%2,%3};"
        : "+f"(c0), "+f"(c1), "+f"(c2), "+f"(c3)
        : "r"(a0), "r"(a1), "r"(a2), "r"(a3), "r"(b0), "r"(b1));
}

// ===========================================================================
// transpose + convert: w6 fp32 [1024][131072] -> g_w6t fp16 [131072][1024]
// 32x32 tiles, 256 threads (32x8), smem pad 33.
// ===========================================================================
__global__ void __launch_bounds__(256)
transpose_cvt(const float* __restrict__ in, __half* __restrict__ outp)
{
    __shared__ float ts[32][33];
    const int tx = threadIdx.x & 31;
    const int ty = threadIdx.x >> 5;
    const int n0 = blockIdx.x * 32;
    const int k0 = blockIdx.y * 32;

#pragma unroll
    for (int i = 0; i < 4; i++)
        ts[ty + 8 * i][tx] = in[(size_t)(k0 + ty + 8 * i) * NOUTCOL + n0 + tx];
    __syncthreads();
#pragma unroll
    for (int i = 0; i < 4; i++)
        outp[(size_t)(n0 + ty + 8 * i) * 1024 + k0 + tx] =
            __float2half(ts[tx][ty + 8 * i]);
}

// ===========================================================================
// GEMM6 fp16: out = epilogue( d2h(512x1024) @ w6t^T + b6 )
// CTA 128(M) x 128(N), K-step 16, 4-stage cp.async, 8 warps (2M x 4N),
// warp tile 64x32 (warp-uniform t). SMEM pitch 24 halfs -> frag-load banks
// 12g+q (all 32 distinct).
// ===========================================================================
#define G6_STG    4
#define G6_PITCH  24                       // halfs per row (16 data + 8 pad)
#define G6_TILEH  (128 * G6_PITCH)         // 3072 halfs = 6144 B per stage
#define G6_NKT    64                       // 1024 / 16

__global__ void __launch_bounds__(256, 2)
gemm6_fp16(const __half* __restrict__ Ah,   // d2h: 512 x 1024
           const __half* __restrict__ Bt,   // w6t: 131072 x 1024
           const float* __restrict__ bias,  // b6: 131072
           const float* __restrict__ low,   // 512 x 256 x 32
           float* __restrict__ out)         // 512 x 4096 x 32
{
    __shared__ __half As[G6_STG][G6_TILEH];
    __shared__ __half Bs[G6_STG][G6_TILEH];
    __shared__ float sbias[128];

    const int tid  = threadIdx.x;
    const int wid  = tid >> 5;
    const int lane = tid & 31;
    const int g    = lane >> 2;    // 0..7
    const int q    = lane & 3;     // 0..3

    const int bm = blockIdx.x * 128;   // 4 M-blocks, fastest -> share w6 in L2
    const int bn = blockIdx.y * 128;   // 1024 N-blocks

    const int wm = (wid >> 2) * 64;
    const int wn = (wid & 3) * 32;

    if (tid < 128) sbias[tid] = bias[bn + tid];

    // cp.async coordinates: both tiles are 128 rows x 16 halfs
    const int row = tid >> 1;
    const int hf  = tid & 1;
    const __half* aSrc = Ah + (size_t)(bm + row) * 1024 + hf * 8;
    const __half* bSrc = Bt + (size_t)(bn + row) * 1024 + hf * 8;
    const uint32_t aDst = smem_u32(&As[0][0]) + (uint32_t)(row * G6_PITCH + hf * 8) * 2;
    const uint32_t bDst = smem_u32(&Bs[0][0]) + (uint32_t)(row * G6_PITCH + hf * 8) * 2;

#define G6_LOAD(s, kt)                                                \
    do {                                                              \
        cp16_ca(aDst + (s) * (G6_TILEH * 2), aSrc + (kt) * 16);       \
        cp16_cg(bDst + (s) * (G6_TILEH * 2), bSrc + (kt) * 16);       \
    } while (0)

    G6_LOAD(0, 0); CP_COMMIT();
    G6_LOAD(1, 1); CP_COMMIT();
    G6_LOAD(2, 2); CP_COMMIT();

    float acc[4][4][4];
#pragma unroll
    for (int i = 0; i < 4; i++)
#pragma unroll
        for (int j = 0; j < 4; j++)
#pragma unroll
            for (int k = 0; k < 4; k++) acc[i][j][k] = 0.0f;

    for (int kt = 0; kt < G6_NKT; kt++) {
        const int s = kt & (G6_STG - 1);
        CP_WAIT2();
        __syncthreads();
        if (kt + 3 < G6_NKT) {
            G6_LOAD((kt + 3) & (G6_STG - 1), kt + 3);
        }
        CP_COMMIT();

        const __half* as = &As[s][0];
        const __half* bs = &Bs[s][0];

        // B fragments (half2 as u32)
        uint32_t bf[4][2];
#pragma unroll
        for (int nt = 0; nt < 4; nt++) {
            const int n = wn + nt * 8 + g;
            bf[nt][0] = *reinterpret_cast<const uint32_t*>(bs + n * G6_PITCH + 2 * q);
            bf[nt][1] = *reinterpret_cast<const uint32_t*>(bs + n * G6_PITCH + 2 * q + 8);
        }
#pragma unroll
        for (int mt = 0; mt < 4; mt++) {
            const int r0 = wm + mt * 16 + g;
            uint32_t a0 = *reinterpret_cast<const uint32_t*>(as + r0 * G6_PITCH + 2 * q);
            uint32_t a1 = *reinterpret_cast<const uint32_t*>(as + (r0 + 8) * G6_PITCH + 2 * q);
            uint32_t a2 = *reinterpret_cast<const uint32_t*>(as + r0 * G6_PITCH + 2 * q + 8);
            uint32_t a3 = *reinterpret_cast<const uint32_t*>(as + (r0 + 8) * G6_PITCH + 2 * q + 8);
#pragma unroll
            for (int nt = 0; nt < 4; nt++)
                mma_fp16(acc[mt][nt][0], acc[mt][nt][1],
                         acc[mt][nt][2], acc[mt][nt][3],
                         a0, a1, a2, a3, bf[nt][0], bf[nt][1]);
        }
    }

    // ---- fused epilogue (warp-uniform t) ----
    const int t   = (bn + wn) >> 5;
    const int rem = t & 15;
    const int seg = t >> 4;
    const bool knot  = (rem == 0);
    const bool inseg = (!knot) && (t < LAST_KNOT);
    const float alpha = (float)rem * 0.0625f;
    const int segB = (seg < NL - 1) ? seg + 1 : NL - 1;

#pragma unroll
    for (int mt = 0; mt < 4; mt++) {
#pragma unroll
        for (int h = 0; h < 2; h++) {
            const int r = bm + wm + mt * 16 + g + h * 8;
            const float* lowr = low + (size_t)r * (NL * NF);
            float* outr = out + (size_t)r * NOUTCOL + bn + wn;
#pragma unroll
            for (int nt = 0; nt < 4; nt++) {
                const int f = nt * 8 + 2 * q;
                float dec0 = acc[mt][nt][2 * h]     + sbias[wn + f];
                float dec1 = acc[mt][nt][2 * h + 1] + sbias[wn + f + 1];
                float2 la = *reinterpret_cast<const float2*>(lowr + seg  * NF + f);
                float2 lb = *reinterpret_cast<const float2*>(lowr + segB * NF + f);
                float lin0 = (1.0f - alpha) * la.x + alpha * lb.x;
                float lin1 = (1.0f - alpha) * la.y + alpha * lb.y;
                float r0 = knot ? la.x : (inseg ? 0.8f * lin0 + 0.2f * dec0 : dec0);
                float r1 = knot ? la.y : (inseg ? 0.8f * lin1 + 0.2f * dec1 : dec1);
                *reinterpret_cast<float2*>(outr + f) = make_float2(r0, r1);
            }
        }
    }
#undef G6_LOAD
}

// ===========================================================================
// Small-layer SIMT SGEMM, templated output type (fp32 or fp16 store)
// ===========================================================================
__device__ __forceinline__ void store4(float* p, float4 v) {
    *reinterpret_cast<float4*>(p) = v;
}
__device__ __forceinline__ void store4(__half* p, float4 v) {
    __half2 h0 = __floats2half2_rn(v.x, v.y);
    __half2 h1 = __floats2half2_rn(v.z, v.w);
    *reinterpret_cast<__half2*>(p)     = h0;
    *reinterpret_cast<__half2*>(p + 2) = h1;
}

template <int BM, int BN, int BK, int TM, int TN, bool RELU, typename OutT>
__global__ __launch_bounds__((BM / TM) * (BN / TN))
void sgemm_bias(const float* __restrict__ A, const float* __restrict__ Bm,
                const float* __restrict__ bias, OutT* __restrict__ C,
                int M, int N, int K)
{
    constexpr int THREADS = (BM / TM) * (BN / TN);
    __shared__ float As[BK][BM + 4];
    __shared__ float Bs[BK][BN];

    const int tid = threadIdx.x;
    const int bn  = blockIdx.x * BN;
    const int bm  = blockIdx.y * BM;
    const int tx  = tid % (BN / TN);
    const int ty  = tid / (BN / TN);

    float acc[TM][TN];
#pragma unroll
    for (int i = 0; i < TM; i++)
#pragma unroll
        for (int j = 0; j < TN; j++) acc[i][j] = 0.0f;

    constexpr int AV = BK / 4;
    constexpr int AT = BM * AV;
    constexpr int BV = BN / 4;
    constexpr int BT = BK * BV;

    for (int k0 = 0; k0 < K; k0 += BK) {
        for (int i = tid; i < AT; i += THREADS) {
            int r  = i / AV;
            int c4 = (i % AV) * 4;
            float4 v = *reinterpret_cast<const float4*>(
                A + (size_t)(bm + r) * K + k0 + c4);
            As[c4 + 0][r] = v.x;
            As[c4 + 1][r] = v.y;
            As[c4 + 2][r] = v.z;
            As[c4 + 3][r] = v.w;
        }
        for (int i = tid; i < BT; i += THREADS) {
            int r  = i / BV;
            int c4 = (i % BV) * 4;
            *reinterpret_cast<float4*>(&Bs[r][c4]) =
                *reinterpret_cast<const float4*>(
                    Bm + (size_t)(k0 + r) * N + bn + c4);
        }
        __syncthreads();

#pragma unroll
        for (int kk = 0; kk < BK; kk++) {
            float ra[TM], rb[TN];
#pragma unroll
            for (int i = 0; i < TM; i += 4)
                *reinterpret_cast<float4*>(&ra[i]) =
                    *reinterpret_cast<const float4*>(&As[kk][ty * TM + i]);
#pragma unroll
            for (int j = 0; j < TN; j += 4)
                *reinterpret_cast<float4*>(&rb[j]) =
                    *reinterpret_cast<const float4*>(&Bs[kk][tx * TN + j]);
#pragma unroll
            for (int i = 0; i < TM; i++)
#pragma unroll
                for (int j = 0; j < TN; j++)
                    acc[i][j] = fmaf(ra[i], rb[j], acc[i][j]);
        }
        __syncthreads();
    }

#pragma unroll
    for (int i = 0; i < TM; i++) {
        int row = bm + ty * TM + i;
#pragma unroll
        for (int j = 0; j < TN; j += 4) {
            int col = bn + tx * TN + j;
            float4 v;
            v.x = acc[i][j + 0] + bias[col + 0];
            v.y = acc[i][j + 1] + bias[col + 1];
            v.z = acc[i][j + 2] + bias[col + 2];
            v.w = acc[i][j + 3] + bias[col + 3];
            if (RELU) {
                v.x = fmaxf(v.x, 0.0f);
                v.y = fmaxf(v.y, 0.0f);
                v.z = fmaxf(v.z, 0.0f);
                v.w = fmaxf(v.w, 0.0f);
            }
            store4(C + (size_t)row * N + col, v);
        }
    }
}

// ---------------------------------------------------------------------------
extern "C" void kernel_launch(void* const* d_in, const int* in_sizes, int n_in,
                              void* d_out, int out_size)
{
    const float* low = (const float*)d_in[0];
    const float* w1  = (const float*)d_in[1];
    const float* b1  = (const float*)d_in[2];
    const float* w2  = (const float*)d_in[3];
    const float* b2  = (const float*)d_in[4];
    const float* w3  = (const float*)d_in[5];
    const float* b3  = (const float*)d_in[6];
    const float* w4  = (const float*)d_in[7];
    const float* b4  = (const float*)d_in[8];
    const float* w5  = (const float*)d_in[9];
    const float* b5  = (const float*)d_in[10];
    const float* w6  = (const float*)d_in[11];
    const float* b6  = (const float*)d_in[12];
    float* out = (float*)d_out;

    float  *h1, *h2, *fe, *d1;
    __half *d2h, *w6t;
    cudaGetSymbolAddress((void**)&h1,  g_h1);
    cudaGetSymbolAddress((void**)&h2,  g_h2);
    cudaGetSymbolAddress((void**)&fe,  g_fe);
    cudaGetSymbolAddress((void**)&d1,  g_d1);
    cudaGetSymbolAddress((void**)&d2h, g_d2h);
    cudaGetSymbolAddress((void**)&w6t, g_w6t);

    // w6 -> fp16 transposed [n][k]
    transpose_cvt<<<dim3(NOUTCOL / 32, 1024 / 32), 256>>>(w6, w6t);

    // L1: (512x8192)@(8192x1024) + relu
    sgemm_bias<64, 64, 16, 4, 4, true, float>
        <<<dim3(1024 / 64, 512 / 64), 256>>>(low, w1, b1, h1, 512, 1024, 8192);
    // L2: (512x1024)@(1024x512) + relu
    sgemm_bias<64, 64, 16, 4, 4, true, float>
        <<<dim3(512 / 64, 512 / 64), 256>>>(h1, w2, b2, h2, 512, 512, 1024);
    // L3: (512x512)@(512x256)
    sgemm_bias<64, 64, 16, 4, 4, false, float>
        <<<dim3(256 / 64, 512 / 64), 256>>>(h2, w3, b3, fe, 512, 256, 512);
    // L4: (512x256)@(256x512) + relu
    sgemm_bias<64, 64, 16, 4, 4, true, float>
        <<<dim3(512 / 64, 512 / 64), 256>>>(fe, w4, b4, d1, 512, 512, 256);
    // L5: (512x512)@(512x1024) + relu, fp16 output
    sgemm_bias<64, 64, 16, 4, 4, true, __half>
        <<<dim3(1024 / 64, 512 / 64), 256>>>(d1, w5, b5, d2h, 512, 1024, 512);
    // L6: fp16 mma + fused epilogue (M-blocks fastest for w6 L2 sharing)
    gemm6_fp16<<<dim3(4, NOUTCOL / 128), 256>>>(d2h, w6t, b6, low, out);
}